// round 10
// baseline (speedup 1.0000x reference)
#include <cuda_runtime.h>
#include <cstdint>

#define PI  3.14159265358979323846f
#define PIH 1.57079632679489662f
#define IR2 0.70710678118654752f

// 16 MB scratch between passes (fits in L2).
// Layout (scalar floats): addr(rtop, l) = (rtop>>1)<<12 | (l>>1)<<2 | 2*(l&1) | (rtop&1)
// => pass B float2 load: g_scr[(g<<11) + l] has lanes (rtop=2g, 2g+1) at row l.
__device__ float2 g_scr[1 << 21];

__device__ __forceinline__ float sin_ap(float x){ float y; asm("sin.approx.f32 %0, %1;" : "=f"(y) : "f"(x)); return y; }
__device__ __forceinline__ float sqrt_ap(float x){ float y; asm("sqrt.approx.f32 %0, %1;" : "=f"(y) : "f"(x)); return y; }
// float2-tile swizzle (bijective: XORs high bits into bits 0-3)
__device__ __forceinline__ int swz(int r){ return r ^ ((r >> 4) & 7) ^ (((r >> 5) & 3) << 2); }

// squared-magnitude butterfly
__device__ __forceinline__ void bfly(float& Se, float& So, float c){
    float r  = sqrt_ap(fmaxf(Se * So, 0.f));
    float T  = c * r;
    float Sp = Se + So;
    Se = fmaf( 2.f, T, Sp);
    So = fmaf(-2.f, T, Sp);
}

struct Coef { float c1, cH, msH, q0, q1, q2, q3; };

__device__ __forceinline__ Coef mkcoef(float h4){
    Coef k;
    float s4 = sin_ap(h4), c4 = sin_ap(PIH - h4);
    float sH = 2.f * s4 * c4;
    float cH = fmaf(-2.f * s4, s4, 1.f);
    k.c1  = fmaf(2.f * cH, cH, -1.f);
    k.cH  = cH;  k.msH = -sH;
    k.q0  = c4;
    k.q1  = (c4 - s4) * IR2;
    k.q2  = -s4;
    k.q3  = -(c4 + s4) * IR2;
    return k;
}

__device__ __forceinline__ void r8A_apply(float* v, const Coef& k){
    bfly(v[0],v[1],k.c1);  bfly(v[2],v[3],k.c1);  bfly(v[4],v[5],k.c1);  bfly(v[6],v[7],k.c1);
    bfly(v[0],v[2],k.cH);  bfly(v[1],v[3],k.msH); bfly(v[4],v[6],k.cH);  bfly(v[5],v[7],k.msH);
    bfly(v[0],v[4],k.q0);  bfly(v[1],v[5],k.q1);  bfly(v[2],v[6],k.q2);  bfly(v[3],v[7],k.q3);
}
__device__ __forceinline__ void r8B_apply(float* v, const Coef& k){
    bfly(v[0],v[4],k.c1);  bfly(v[1],v[5],k.c1);  bfly(v[2],v[6],k.c1);  bfly(v[3],v[7],k.c1);
    bfly(v[0],v[2],k.cH);  bfly(v[1],v[3],k.cH);  bfly(v[4],v[6],k.msH); bfly(v[5],v[7],k.msH);
    bfly(v[0],v[1],k.q0);  bfly(v[2],v[3],k.q2);  bfly(v[4],v[5],k.q1);  bfly(v[6],v[7],k.q3);
}

// Pass A round (stages B+1..B+3): thread handles groups t and t+128, SAME twiddle
template<int B>
__device__ __forceinline__ void r8A2(float2* tile, int t){
    const int j0 = t & ((1 << B) - 1);
    Coef k = mkcoef((float)j0 * (PI / (float)(4 << B)));
    #pragma unroll
    for (int gg = 0; gg < 2; gg++){
        int g = t + (gg << 7);
        int base = ((g >> B) << (B + 3)) | j0;
        int idx[8]; float2 v[8]; float a[8];
        #pragma unroll
        for (int n = 0; n < 8; n++){ idx[n] = swz(base + (n << B)); v[n] = tile[idx[n]]; }
        #pragma unroll
        for (int n = 0; n < 8; n++) a[n] = v[n].x;
        r8A_apply(a, k);
        #pragma unroll
        for (int n = 0; n < 8; n++){ v[n].x = a[n]; a[n] = v[n].y; }
        r8A_apply(a, k);
        #pragma unroll
        for (int n = 0; n < 8; n++){ v[n].y = a[n]; tile[idx[n]] = v[n]; }
    }
}

// Pass B round: groups t, t+128; per-lane twiddles
template<int B>
__device__ __forceinline__ void r8B2(float2* tile, int t, int R0){
    const int   mtop = (1 << (8 - B)) - 1;
    const float sc   = PI / (float)(1 << (21 - B));
    #pragma unroll
    for (int gg = 0; gg < 2; gg++){
        int g = t + (gg << 7);
        int base = ((g >> B) << (B + 3)) | (g & ((1 << B) - 1));
        int rl = (int)(__brev((unsigned)base) >> 21);
        float h0 = (float)(((rl & mtop) << 11) + R0) * sc;
        int idx[8]; float2 v[8]; float a[8];
        #pragma unroll
        for (int n = 0; n < 8; n++){ idx[n] = swz(base + (n << B)); v[n] = tile[idx[n]]; }
        {   Coef k = mkcoef(h0);
            #pragma unroll
            for (int n = 0; n < 8; n++) a[n] = v[n].x;
            r8B_apply(a, k);
            #pragma unroll
            for (int n = 0; n < 8; n++) v[n].x = a[n];
        }
        {   Coef k = mkcoef(h0 + sc);
            #pragma unroll
            for (int n = 0; n < 8; n++) a[n] = v[n].y;
            r8B_apply(a, k);
            #pragma unroll
            for (int n = 0; n < 8; n++){ v[n].y = a[n]; tile[idx[n]] = v[n]; }
        }
    }
}

// ================= Pass A: stages 1..11 ; 1024 blocks x 128 threads =================
__global__ void __launch_bounds__(128) fftA(const float2* __restrict__ x2){
    __shared__ float2 tile[2048];     // 16 KB
    const int t  = threadIdx.x;
    const int lb = blockIdx.x;        // lanes l = 2lb, 2lb+1

    // round 1: stages 1-3 (const twiddles) in registers; rows (gg<<10)+8t+n
    #pragma unroll
    for (int gg = 0; gg < 2; gg++){
        float2 v[8];
        #pragma unroll
        for (int n = 0; n < 8; n++){
            int r = (gg << 10) | (t << 3) | n;
            int T = (int)(__brev((unsigned)r) >> 21);
            v[n] = x2[(T << 10) + lb];
        }
        float2 S[8];
#define R1(L) { \
        float a0=fabsf(v[0].L+v[1].L), a1=fabsf(v[0].L-v[1].L); \
        float a2=fabsf(v[2].L+v[3].L), a3=fabsf(v[2].L-v[3].L); \
        float a4=fabsf(v[4].L+v[5].L), a5=fabsf(v[4].L-v[5].L); \
        float a6=fabsf(v[6].L+v[7].L), a7=fabsf(v[6].L-v[7].L); \
        float s0=a0+a2, d0=a0-a2; float S0=s0*s0, S2=d0*d0; \
        float S1=fmaf(a1,a1,a3*a3);  float S3=S1; \
        float s4=a4+a6, d4=a4-a6; float S4=s4*s4, S6=d4*d4; \
        float S5=fmaf(a5,a5,a7*a7);  float S7=S5; \
        bfly(S0,S4,1.f); bfly(S1,S5,IR2); \
        float tz=S2+S6; S2=tz; S6=tz; \
        bfly(S3,S7,-IR2); \
        S[0].L=S0; S[1].L=S1; S[2].L=S2; S[3].L=S3; \
        S[4].L=S4; S[5].L=S5; S[6].L=S6; S[7].L=S7; }
        R1(x) R1(y)
#undef R1
        #pragma unroll
        for (int n = 0; n < 8; n++) tile[swz((gg << 10) | (t << 3) | n)] = S[n];
    }
    __syncthreads();

    r8A2<3>(tile, t); __syncthreads();   // stages 4,5,6
    r8A2<6>(tile, t); __syncthreads();   // stages 7,8,9

    // final radix-4 (stages 10,11) + TRANSPOSED store to scratch
    // addr(r, l=2lb)   = (r>>1)<<12 | lb<<2 | (r&1)       (component x)
    // addr(r, l=2lb+1) = same + 2                          (component y)
    float* scrF = (float*)g_scr;
    #pragma unroll
    for (int m = 0; m < 4; m++){
        int gb = t + (m << 7);
        float h  = (float)gb * (PI / 1024.f);
        float sH = sin_ap(h), cH = sin_ap(PIH - h);
        float c1 = fmaf(-2.f * sH, sH, 1.f), msH = -sH;
        float2 v0 = tile[swz(gb)];
        float2 v1 = tile[swz(gb + 512)];
        float2 v2 = tile[swz(gb + 1024)];
        float2 v3 = tile[swz(gb + 1536)];
#define R4A(L) { bfly(v0.L, v1.L, c1); bfly(v2.L, v3.L, c1); \
                 bfly(v0.L, v2.L, cH); bfly(v1.L, v3.L, msH); }
        R4A(x) R4A(y)
#undef R4A
        #pragma unroll
        for (int kk = 0; kk < 4; kk++){
            int r = gb + (kk << 9);
            const float2& vv = (kk == 0) ? v0 : (kk == 1) ? v1 : (kk == 2) ? v2 : v3;
            int a = ((r >> 1) << 12) + (lb << 2) + (r & 1);
            scrF[a]     = vv.x;
            scrF[a + 2] = vv.y;
        }
    }
}

// ================= Pass B: stages 12..22 + sqrt + bit-reversed store =================
__global__ void __launch_bounds__(128) fftB(float2* __restrict__ out2){
    __shared__ float2 tile[2048];
    const int t  = threadIdx.x;
    const int g  = blockIdx.x;        // lanes rB = 2g, 2g+1
    const int R0 = g << 1;

    // round 1 (stages 12,13,14): register-forwarded coalesced load; jb = R0
    {
        const float sc = PI / (float)(1 << 13);
        float h0 = (float)R0 * sc;
        Coef k0 = mkcoef(h0), k1 = mkcoef(h0 + sc);
        #pragma unroll
        for (int gg = 0; gg < 2; gg++){
            float2 v[8]; float a[8];
            const float2* src = g_scr + ((long)g << 11) + t + (gg << 7);
            #pragma unroll
            for (int n = 0; n < 8; n++) v[n] = src[n << 8];
            #pragma unroll
            for (int n = 0; n < 8; n++) a[n] = v[n].x;
            r8B_apply(a, k0);
            #pragma unroll
            for (int n = 0; n < 8; n++){ v[n].x = a[n]; a[n] = v[n].y; }
            r8B_apply(a, k1);
            #pragma unroll
            for (int n = 0; n < 8; n++){ v[n].y = a[n];
                tile[swz(t + (gg << 7) + (n << 8))] = v[n]; }
        }
    }
    __syncthreads();

    r8B2<5>(tile, t, R0); __syncthreads();   // stages 15,16,17
    r8B2<2>(tile, t, R0); __syncthreads();   // stages 18,19,20

    // final radix-4 (stages 21,22) + sqrt + bit-reversed store
    {
        const float hs = PI / (float)(1 << 21);
        #pragma unroll
        for (int m = 0; m < 4; m++){
            int gb   = t + (m << 7);
            int base = gb << 2;
            int rl = (int)(__brev((unsigned)base) >> 21);
            float h0 = (float)(((rl & 511) << 11) + R0) * hs;
            float2 v0 = tile[swz(base)];
            float2 v1 = tile[swz(base + 1)];
            float2 v2 = tile[swz(base + 2)];
            float2 v3 = tile[swz(base + 3)];
#define RLF(L, HH) { float h = (HH); \
            float sh = sin_ap(h), ch = sin_ap(PIH - h); \
            float c2 = fmaf(-2.f * sh, sh, 1.f); float msh = -sh; \
            bfly(v0.L, v2.L, c2); bfly(v1.L, v3.L, c2); \
            bfly(v0.L, v1.L, ch); bfly(v2.L, v3.L, msh); }
            RLF(x, h0) RLF(y, h0 + hs)
#undef RLF
#define SQ2(v) make_float2(sqrt_ap(fmaxf(v.x,0.f)), sqrt_ap(fmaxf(v.y,0.f)))
            out2[(((int)(__brev((unsigned)(base + 0)) >> 21)) << 10) + g] = SQ2(v0);
            out2[(((int)(__brev((unsigned)(base + 1)) >> 21)) << 10) + g] = SQ2(v1);
            out2[(((int)(__brev((unsigned)(base + 2)) >> 21)) << 10) + g] = SQ2(v2);
            out2[(((int)(__brev((unsigned)(base + 3)) >> 21)) << 10) + g] = SQ2(v3);
#undef SQ2
        }
    }
}

extern "C" void kernel_launch(void* const* d_in, const int* in_sizes, int n_in,
                              void* d_out, int out_size) {
    const float2* x2 = (const float2*)d_in[0];
    fftA<<<1024, 128>>>(x2);
    fftB<<<1024, 128>>>((float2*)d_out);
}

// round 11
// speedup vs baseline: 1.3818x; 1.3818x over previous
#include <cuda_runtime.h>
#include <cstdint>

#define PI  3.14159265358979323846f
#define PIH 1.57079632679489662f
#define IR2 0.70710678118654752f

// 16 MB scratch between passes (fits in L2)
__device__ float4 g_scr[1 << 20];

__device__ __forceinline__ float sin_ap(float x){ float y; asm("sin.approx.f32 %0, %1;" : "=f"(y) : "f"(x)); return y; }
__device__ __forceinline__ float sqrt_ap(float x){ float y; asm("sqrt.approx.f32 %0, %1;" : "=f"(y) : "f"(x)); return y; }
// conflict-free for float4 tiles at the strided patterns used
__device__ __forceinline__ int swz(int r){ return r ^ ((r >> 4) & 3) ^ (((r >> 5) & 3) << 2); }

// squared-magnitude butterfly; clamp product (tiny negatives from rounding)
__device__ __forceinline__ void bfly(float& Se, float& So, float c){
    float r  = sqrt_ap(fmaxf(Se * So, 0.f));
    float T  = c * r;
    float Sp = Se + So;
    Se = fmaf( 2.f, T, Sp);
    So = fmaf(-2.f, T, Sp);
}

struct Coef { float c1, cH, msH, q0, q1, q2, q3; };

// radix-8 twiddles from quarter-angle (s4, c4) = (sin h4, cos h4)
__device__ __forceinline__ Coef mkcoef_sc(float s4, float c4){
    Coef k;
    float sH = 2.f * s4 * c4;
    float cH = fmaf(-2.f * s4, s4, 1.f);
    k.c1  = fmaf(2.f * cH, cH, -1.f);
    k.cH  = cH;  k.msH = -sH;
    k.q0  = c4;
    k.q1  = (c4 - s4) * IR2;
    k.q2  = -s4;
    k.q3  = -(c4 + s4) * IR2;
    return k;
}
__device__ __forceinline__ Coef mkcoef(float h4){
    return mkcoef_sc(sin_ap(h4), sin_ap(PIH - h4));
}

// Pass A: stages pair ascending bits
__device__ __forceinline__ void r8A_apply(float* v, const Coef& k){
    bfly(v[0],v[1],k.c1);  bfly(v[2],v[3],k.c1);  bfly(v[4],v[5],k.c1);  bfly(v[6],v[7],k.c1);
    bfly(v[0],v[2],k.cH);  bfly(v[1],v[3],k.msH); bfly(v[4],v[6],k.cH);  bfly(v[5],v[7],k.msH);
    bfly(v[0],v[4],k.q0);  bfly(v[1],v[5],k.q1);  bfly(v[2],v[6],k.q2);  bfly(v[3],v[7],k.q3);
}
// Pass B: stages pair descending bits
__device__ __forceinline__ void r8B_apply(float* v, const Coef& k){
    bfly(v[0],v[4],k.c1);  bfly(v[1],v[5],k.c1);  bfly(v[2],v[6],k.c1);  bfly(v[3],v[7],k.c1);
    bfly(v[0],v[2],k.cH);  bfly(v[1],v[3],k.cH);  bfly(v[4],v[6],k.msH); bfly(v[5],v[7],k.msH);
    bfly(v[0],v[1],k.q0);  bfly(v[2],v[3],k.q2);  bfly(v[4],v[5],k.q1);  bfly(v[6],v[7],k.q3);
}

template<int B>
__device__ __forceinline__ void r8A(float4* tile, int t){
    const int   j0   = t & ((1 << B) - 1);
    const int   base = ((t >> B) << (B + 3)) | j0;
    const float h4   = (float)j0 * (PI / (float)(4 << B));
    Coef k = mkcoef(h4);
    int idx[8]; float4 v[8]; float a[8];
    #pragma unroll
    for (int n = 0; n < 8; n++){ idx[n] = swz(base + (n << B)); v[n] = tile[idx[n]]; }
    #pragma unroll
    for (int n = 0; n < 8; n++) a[n] = v[n].x;
    r8A_apply(a, k);
    #pragma unroll
    for (int n = 0; n < 8; n++){ v[n].x = a[n]; a[n] = v[n].y; }
    r8A_apply(a, k);
    #pragma unroll
    for (int n = 0; n < 8; n++){ v[n].y = a[n]; a[n] = v[n].z; }
    r8A_apply(a, k);
    #pragma unroll
    for (int n = 0; n < 8; n++){ v[n].z = a[n]; a[n] = v[n].w; }
    r8A_apply(a, k);
    #pragma unroll
    for (int n = 0; n < 8; n++){ v[n].w = a[n]; tile[idx[n]] = v[n]; }
}

// pass-B radix-8 on registers; per-lane quarter-angle advanced by FMA rotation
// (ss = sin(sc) = sc in fp32 for all sc used; cc = cos(sc) = 1 - sc^2/2)
__device__ __forceinline__ void r8B_regs_rot(float4* v, float s4, float c4,
                                             float ss, float cc){
    float a[8];
    {   Coef k = mkcoef_sc(s4, c4);
        #pragma unroll
        for (int n = 0; n < 8; n++) a[n] = v[n].x;
        r8B_apply(a, k);
        #pragma unroll
        for (int n = 0; n < 8; n++) v[n].x = a[n];
    }
    float s1 = fmaf(c4, ss, s4 * cc), c1 = fmaf(-s4, ss, c4 * cc);
    {   Coef k = mkcoef_sc(s1, c1);
        #pragma unroll
        for (int n = 0; n < 8; n++) a[n] = v[n].y;
        r8B_apply(a, k);
        #pragma unroll
        for (int n = 0; n < 8; n++) v[n].y = a[n];
    }
    float s2 = fmaf(c1, ss, s1 * cc), c2 = fmaf(-s1, ss, c1 * cc);
    {   Coef k = mkcoef_sc(s2, c2);
        #pragma unroll
        for (int n = 0; n < 8; n++) a[n] = v[n].z;
        r8B_apply(a, k);
        #pragma unroll
        for (int n = 0; n < 8; n++) v[n].z = a[n];
    }
    float s3 = fmaf(c2, ss, s2 * cc), c3 = fmaf(-s2, ss, c2 * cc);
    {   Coef k = mkcoef_sc(s3, c3);
        #pragma unroll
        for (int n = 0; n < 8; n++) a[n] = v[n].w;
        r8B_apply(a, k);
        #pragma unroll
        for (int n = 0; n < 8; n++) v[n].w = a[n];
    }
}

template<int B>
__device__ __forceinline__ void r8B(float4* tile, int t, int R0){
    const int   mtop = (1 << (8 - B)) - 1;
    const int   base = ((t >> B) << (B + 3)) | (t & ((1 << B) - 1));
    const float sc   = PI / (float)(1 << (21 - B));
    const float cc   = 1.f - 0.5f * sc * sc;
    int   rl = (int)(__brev((unsigned)base) >> 21);
    int   jb = ((rl & mtop) << 11) + R0;
    float h0 = (float)jb * sc;
    int idx[8]; float4 v[8];
    #pragma unroll
    for (int n = 0; n < 8; n++){ idx[n] = swz(base + (n << B)); v[n] = tile[idx[n]]; }
    float s0 = sin_ap(h0), c0 = sin_ap(PIH - h0);
    r8B_regs_rot(v, s0, c0, sc, cc);
    #pragma unroll
    for (int n = 0; n < 8; n++) tile[idx[n]] = v[n];
}

// ================= Pass A: stages 1..11 =================
__global__ void __launch_bounds__(256) fftA(const float4* __restrict__ x4){
    __shared__ float4 tile[2048];
    const int t   = threadIdx.x;
    const int lb4 = blockIdx.x;
    const int w   = t >> 5, ln = t & 31;

    // fused load + closed-form stages (1,2)
    #pragma unroll
    for (int m = 0; m < 2; m++){
        int g = (w << 6) | ln | (m << 5);
        int b = g << 2;
        float4 e0 = x4[(((int)(__brev((unsigned)(b + 0)) >> 21)) << 9) + lb4];
        float4 e1 = x4[(((int)(__brev((unsigned)(b + 1)) >> 21)) << 9) + lb4];
        float4 e2 = x4[(((int)(__brev((unsigned)(b + 2)) >> 21)) << 9) + lb4];
        float4 e3 = x4[(((int)(__brev((unsigned)(b + 3)) >> 21)) << 9) + lb4];
        float4 w0, w1, w2;
#define G12(L) { \
        float A  = fabsf(e0.L + e1.L), Bv = fabsf(e2.L + e3.L); \
        float d1 = e0.L - e1.L,        d2 = e2.L - e3.L;        \
        float s  = A + Bv,             q  = A - Bv;             \
        w0.L = s * s; w2.L = q * q; w1.L = fmaf(d1, d1, d2 * d2); }
        G12(x) G12(y) G12(z) G12(w)
#undef G12
        tile[swz(b)] = w0; tile[swz(b + 1)] = w1; tile[swz(b + 2)] = w2; tile[swz(b + 3)] = w1;
    }
    __syncwarp();

    r8A<2>(tile, t); __syncwarp();      // stages 3,4,5 (warp-local rows)
    r8A<5>(tile, t); __syncthreads();   // stages 6,7,8
    r8A<8>(tile, t); __syncthreads();   // stages 9,10,11

    // transpose-store to scratch (pass-B layout)
    const float* ts  = (const float*)tile;
    float*       scr = (float*)g_scr;
    #pragma unroll
    for (int e = t; e < 8192; e += 256){
        int r0 = e & 3, li = (e >> 2) & 3, G = e >> 4;
        int r  = (G << 2) | r0;
        scr[(G << 13) + (((lb4 << 2) + li) << 2) + r0] = ts[swz(r) * 4 + li];
    }
}

// ================= Pass B: stages 12..22 + sqrt + bit-reversed store =================
__global__ void __launch_bounds__(256) fftB(float4* __restrict__ out4){
    __shared__ float4 tile[2048];
    const int t  = threadIdx.x;
    const int g  = blockIdx.x;
    const int R0 = g << 2;
    const int w  = t >> 5, ln = t & 31;

    // round 1 (stages 12,13,14): register-forwarded load (rows t + 256n)
    {
        const float sc = PI / (float)(1 << 13);
        const float cc = 1.f - 0.5f * sc * sc;
        float h0 = (float)R0 * sc;       // jb = R0
        float4 v[8];
        const float4* src = g_scr + ((long)g << 11) + t;
        #pragma unroll
        for (int n = 0; n < 8; n++) v[n] = src[n << 8];
        float s0 = sin_ap(h0), c0 = sin_ap(PIH - h0);
        r8B_regs_rot(v, s0, c0, sc, cc);
        #pragma unroll
        for (int n = 0; n < 8; n++) tile[swz(t + (n << 8))] = v[n];
    }
    __syncthreads();

    r8B<5>(tile, t, R0); __syncwarp();   // stages 15,16,17 (warp-local)
    r8B<2>(tile, t, R0); __syncwarp();   // stages 18,19,20 (warp-local)

    // final radix-4 (stages 21,22) + sqrt + bit-reversed scatter
    {
        const float hs = PI / (float)(1 << 21);   // sin(hs)=hs, cos(hs)=1 in fp32
        #pragma unroll
        for (int m = 0; m < 2; m++){
            int gb   = (w << 6) | ln | (m << 5);
            int base = gb << 2;
            int i00 = swz(base), i01 = swz(base + 1), i10 = swz(base + 2), i11 = swz(base + 3);
            int rl = (int)(__brev((unsigned)base) >> 21);
            int jb = ((rl & 511) << 11) + R0;
            float h0 = (float)jb * hs;
            float4 v00 = tile[i00], v01 = tile[i01], v10 = tile[i10], v11 = tile[i11];
            float sh = sin_ap(h0), ch = sin_ap(PIH - h0);
#define RLF(L) { \
            float c2 = fmaf(-2.f * sh, sh, 1.f); float msh = -sh; \
            bfly(v00.L, v10.L, c2); bfly(v01.L, v11.L, c2); \
            bfly(v00.L, v01.L, ch); bfly(v10.L, v11.L, msh); }
#define ROT()  { float sn = fmaf(ch, hs, sh); ch = fmaf(-sh, hs, ch); sh = sn; }
            RLF(x) ROT()
            RLF(y) ROT()
            RLF(z) ROT()
            RLF(w)
#undef ROT
#undef RLF
#define SQ4(v) make_float4(sqrt_ap(fmaxf(v.x,0.f)), sqrt_ap(fmaxf(v.y,0.f)), \
                           sqrt_ap(fmaxf(v.z,0.f)), sqrt_ap(fmaxf(v.w,0.f)))
            out4[(((int)(__brev((unsigned)(base + 0)) >> 21)) << 9) + g] = SQ4(v00);
            out4[(((int)(__brev((unsigned)(base + 1)) >> 21)) << 9) + g] = SQ4(v01);
            out4[(((int)(__brev((unsigned)(base + 2)) >> 21)) << 9) + g] = SQ4(v10);
            out4[(((int)(__brev((unsigned)(base + 3)) >> 21)) << 9) + g] = SQ4(v11);
#undef SQ4
        }
    }
}

extern "C" void kernel_launch(void* const* d_in, const int* in_sizes, int n_in,
                              void* d_out, int out_size) {
    const float4* x4 = (const float4*)d_in[0];
    fftA<<<512, 256>>>(x4);
    fftB<<<512, 256>>>((float4*)d_out);
}